// round 7
// baseline (speedup 1.0000x reference)
#include <cuda_runtime.h>
#include <cuda_bf16.h>
#include <math.h>
#include <stdint.h>

// Problem constants (fixed shapes)
#define BB 2
#define TT 2048
#define DMM 512
#define HH 8
#define DD 64
#define UU 3
#define KCH 8                      // k-chunks for reduced path
#define KCHLEN (TT / KCH)          // 256
#define XSZ (BB * TT * DMM)        // 2097152
#define WSZ (DMM * DMM)            // 262144
#define LOG2E 1.4426950408889634f

// ---------------- scratch (static device memory; no allocs allowed) ----------
__device__ float g_Q[XSZ];                    // projected Q  [B,T,DM] fp32
__device__ float g_Kp[XSZ];                   // projected K  [B,T,DM] fp32
__device__ __align__(16) __nv_bfloat16 g_Qhi[XSZ];
__device__ __align__(16) __nv_bfloat16 g_Qlo[XSZ];
__device__ __align__(16) __nv_bfloat16 g_Khi[XSZ];
__device__ __align__(16) __nv_bfloat16 g_Klo[XSZ];
__device__ __align__(16) __nv_bfloat16 g_Xhi[2 * XSZ];   // split inputs (q|k)
__device__ __align__(16) __nv_bfloat16 g_Xlo[2 * XSZ];
__device__ __align__(16) __nv_bfloat16 g_Whi[2 * WSZ];   // split weights (Wq|Wk)
__device__ __align__(16) __nv_bfloat16 g_Wlo[2 * WSZ];
__device__ float g_KL[BB * HH * TT];          // KL rank score per query
__device__ float g_Zall[BB * HH * TT];        // softmax Z per query (from kl pass)
__device__ int   g_topk[BB * HH * UU];        // selected query indices
__device__ float g_outred[BB * HH * UU * DD]; // reduced attention outputs
__device__ float g_Tpart[BB * HH * KCH * UU * DMM]; // partial w@V (normalized)

// ---------------- small PTX helpers ------------------------------------------
__device__ __forceinline__ uint32_t smem_u32(const void* p) {
    uint32_t a;
    asm("{ .reg .u64 t; cvta.to.shared.u64 t, %1; cvt.u32.u64 %0, t; }" : "=r"(a) : "l"(p));
    return a;
}
__device__ __forceinline__ void cpa16(uint32_t dst, const void* src) {
    asm volatile("cp.async.cg.shared.global [%0], [%1], 16;\n" :: "r"(dst), "l"(src) : "memory");
}
#define CP_COMMIT() asm volatile("cp.async.commit_group;\n" ::: "memory")
#define CP_WAIT1()  asm volatile("cp.async.wait_group 1;\n" ::: "memory")
#define CP_WAIT0()  asm volatile("cp.async.wait_group 0;\n" ::: "memory")

__device__ __forceinline__ float ex2f(float x) {
    float y;
    asm("ex2.approx.f32 %0, %1;" : "=f"(y) : "f"(x));
    return y;
}

// mma.sync m16n8k16 bf16 -> f32 (sm_80+ PTX; works on compute_100)
__device__ __forceinline__ void mma16816(float* d, const uint32_t* a, uint32_t b0, uint32_t b1) {
    asm volatile(
        "mma.sync.aligned.m16n8k16.row.col.f32.bf16.bf16.f32 "
        "{%0,%1,%2,%3}, {%4,%5,%6,%7}, {%8,%9}, {%0,%1,%2,%3};\n"
        : "+f"(d[0]), "+f"(d[1]), "+f"(d[2]), "+f"(d[3])
        : "r"(a[0]), "r"(a[1]), "r"(a[2]), "r"(a[3]), "r"(b0), "r"(b1));
}

// split float pair -> packed bf16 hi word (returns) and lo word (out-param)
__device__ __forceinline__ uint32_t split2(float a, float b, uint32_t& lw) {
    __nv_bfloat16 ha = __float2bfloat16_rn(a), hb = __float2bfloat16_rn(b);
    __nv_bfloat16 la = __float2bfloat16_rn(a - __bfloat162float(ha));
    __nv_bfloat16 lb = __float2bfloat16_rn(b - __bfloat162float(hb));
    lw = ((uint32_t)__bfloat16_as_ushort(lb) << 16) | __bfloat16_as_ushort(la);
    return ((uint32_t)__bfloat16_as_ushort(hb) << 16) | __bfloat16_as_ushort(ha);
}

// ---------------- K0: convert inputs to bf16 hi/lo ---------------------------
__global__ void convert_kernel(const float4* __restrict__ query, const float4* __restrict__ key,
                               const float4* __restrict__ Wq, const float4* __restrict__ Wk) {
    const int X4 = XSZ / 4, W4 = WSZ / 4;
    int i = blockIdx.x * 256 + threadIdx.x;
    float4 v;
    __nv_bfloat16 *hi, *lo;
    if (i < 2 * X4) {
        int z = (i >= X4) ? 1 : 0;
        int o = i - z * X4;
        v = (z ? key : query)[o];
        hi = g_Xhi + (size_t)z * XSZ + (size_t)o * 4;
        lo = g_Xlo + (size_t)z * XSZ + (size_t)o * 4;
    } else {
        int j = i - 2 * X4;
        if (j >= 2 * W4) return;
        int z = (j >= W4) ? 1 : 0;
        int o = j - z * W4;
        v = (z ? Wk : Wq)[o];
        hi = g_Whi + (size_t)z * WSZ + (size_t)o * 4;
        lo = g_Wlo + (size_t)z * WSZ + (size_t)o * 4;
    }
    uint32_t l01, l23;
    uint32_t h01 = split2(v.x, v.y, l01);
    uint32_t h23 = split2(v.z, v.w, l23);
    *(uint2*)hi = make_uint2(h01, h23);
    *(uint2*)lo = make_uint2(l01, l23);
}

// ---------------- K1: projection GEMM on tensor cores ------------------------
#define PJ_STRIDE 144
#define PJ_XHI 0
#define PJ_XLO 18432
#define PJ_WHI 36864
#define PJ_WLO 46080
#define PJ_BUF 55296
#define PJ_SMEM (2 * PJ_BUF)       // 110592

__device__ __forceinline__ void proj_load_chunk(uint32_t bb, int tid, int rowBase, int colBase,
                                                int j,
                                                const __nv_bfloat16* __restrict__ Xhi,
                                                const __nv_bfloat16* __restrict__ Xlo,
                                                const __nv_bfloat16* __restrict__ Whi,
                                                const __nv_bfloat16* __restrict__ Wlo) {
#pragma unroll
    for (int i = 0; i < 4; i++) {
        int q = tid + 256 * i;                 // 0..1023
        int r = q >> 3, c = q & 7;
        size_t src = (size_t)(rowBase + r) * DMM + j * 64 + c * 8;
        uint32_t d = bb + r * PJ_STRIDE + c * 16;
        cpa16(d + PJ_XHI, Xhi + src);
        cpa16(d + PJ_XLO, Xlo + src);
    }
#pragma unroll
    for (int i = 0; i < 2; i++) {
        int q = tid + 256 * i;                 // 0..511
        int r = q >> 3, c = q & 7;
        size_t src = (size_t)(colBase + r) * DMM + j * 64 + c * 8;
        uint32_t d = bb + r * PJ_STRIDE + c * 16;
        cpa16(d + PJ_WHI, Whi + src);
        cpa16(d + PJ_WLO, Wlo + src);
    }
}

__global__ void __launch_bounds__(256) proj_mma_kernel(const float* __restrict__ bq,
                                                       const float* __restrict__ bk) {
    extern __shared__ char psm[];
    uint32_t sb = smem_u32(psm);
    int tid = threadIdx.x;
    int wid = tid >> 5, lane = tid & 31;
    int wm = wid & 3, wn = wid >> 2;
    int g = lane >> 2, t4 = lane & 3;
    int rowBase = blockIdx.x * 128;
    int colBase = blockIdx.y * 64;
    int z = blockIdx.z;
    const __nv_bfloat16* Xhi = g_Xhi + (size_t)z * XSZ;
    const __nv_bfloat16* Xlo = g_Xlo + (size_t)z * XSZ;
    const __nv_bfloat16* Whi = g_Whi + (size_t)z * WSZ;
    const __nv_bfloat16* Wlo = g_Wlo + (size_t)z * WSZ;
    const float* bias = z ? bk : bq;
    float*         Out = z ? g_Kp  : g_Q;
    __nv_bfloat16* Ohi = z ? g_Khi : g_Qhi;
    __nv_bfloat16* Olo = z ? g_Klo : g_Qlo;

    float acc[2][4][4];
#pragma unroll
    for (int mi = 0; mi < 2; mi++)
#pragma unroll
        for (int ni = 0; ni < 4; ni++)
#pragma unroll
            for (int r = 0; r < 4; r++) acc[mi][ni][r] = 0.f;

    proj_load_chunk(sb, tid, rowBase, colBase, 0, Xhi, Xlo, Whi, Wlo);
    CP_COMMIT();

    for (int j = 0; j < 8; j++) {
        if (j < 7) {
            proj_load_chunk(sb + ((j + 1) & 1) * PJ_BUF, tid, rowBase, colBase, j + 1,
                            Xhi, Xlo, Whi, Wlo);
            CP_COMMIT();
            CP_WAIT1();
        } else {
            CP_WAIT0();
        }
        __syncthreads();
        const char* xb = psm + (j & 1) * PJ_BUF;
        const char* xh = xb + PJ_XHI;
        const char* xl = xb + PJ_XLO;
        const char* wh = xb + PJ_WHI;
        const char* wl = xb + PJ_WLO;
#pragma unroll
        for (int k0 = 0; k0 < 64; k0 += 16) {
            const int cA = (k0 + 2 * t4) * 2;
            const int cB = cA + 16;
            uint32_t aH[2][4], aL[2][4];
#pragma unroll
            for (int mi = 0; mi < 2; mi++) {
                int rA = (wm * 32 + mi * 16 + g) * PJ_STRIDE;
                int rB = rA + 8 * PJ_STRIDE;
                aH[mi][0] = *(const uint32_t*)(xh + rA + cA);
                aH[mi][1] = *(const uint32_t*)(xh + rB + cA);
                aH[mi][2] = *(const uint32_t*)(xh + rA + cB);
                aH[mi][3] = *(const uint32_t*)(xh + rB + cB);
                aL[mi][0] = *(const uint32_t*)(xl + rA + cA);
                aL[mi][1] = *(const uint32_t*)(xl + rB + cA);
                aL[mi][2] = *(const uint32_t*)(xl + rA + cB);
                aL[mi][3] = *(const uint32_t*)(xl + rB + cB);
            }
#pragma unroll
            for (int ni = 0; ni < 4; ni++) {
                int nr = (wn * 32 + ni * 8 + g) * PJ_STRIDE;
                uint32_t bh0 = *(const uint32_t*)(wh + nr + cA);
                uint32_t bh1 = *(const uint32_t*)(wh + nr + cB);
                uint32_t bl0 = *(const uint32_t*)(wl + nr + cA);
                uint32_t bl1 = *(const uint32_t*)(wl + nr + cB);
                mma16816(acc[0][ni], aH[0], bh0, bh1);
                mma16816(acc[1][ni], aH[1], bh0, bh1);
                mma16816(acc[0][ni], aH[0], bl0, bl1);
                mma16816(acc[1][ni], aH[1], bl0, bl1);
                mma16816(acc[0][ni], aL[0], bh0, bh1);
                mma16816(acc[1][ni], aL[1], bh0, bh1);
            }
        }
        __syncthreads();
    }

#pragma unroll
    for (int mi = 0; mi < 2; mi++) {
#pragma unroll
        for (int ni = 0; ni < 4; ni++) {
            int row = rowBase + wm * 32 + mi * 16 + g;
            int col = colBase + wn * 32 + ni * 8 + 2 * t4;
            float b0 = bias[col], b1 = bias[col + 1];
            float v0 = acc[mi][ni][0] + b0, v1 = acc[mi][ni][1] + b1;
            float v2 = acc[mi][ni][2] + b0, v3 = acc[mi][ni][3] + b1;
            size_t p0 = (size_t)row * DMM + col;
            size_t p1 = (size_t)(row + 8) * DMM + col;
            *(float2*)&Out[p0] = make_float2(v0, v1);
            *(float2*)&Out[p1] = make_float2(v2, v3);
            uint32_t lw0, lw1;
            uint32_t hw0 = split2(v0, v1, lw0);
            uint32_t hw1 = split2(v2, v3, lw1);
            *(uint32_t*)&Ohi[p0] = hw0; *(uint32_t*)&Olo[p0] = lw0;
            *(uint32_t*)&Ohi[p1] = hw1; *(uint32_t*)&Olo[p1] = lw1;
        }
    }
}

// ======================= K2: mma.sync fused scores + KL ======================
#define KSTRIDE_B 144                 // 72 bf16 per row
#define OFF_QHI   0
#define OFF_QLO   36864
#define OFF_K     73728               // + buf*36864 (Khi at +0, Klo at +18432)
#define KL_SMEM   147456
#define C_SCALE   0.18033688011112042f   // 0.125 * log2(e)

__device__ __forceinline__ void load_ktile(uint32_t sb, int tid, int b, int h, int j, int buf) {
    const __nv_bfloat16* hiB = g_Khi + ((size_t)b * TT) * DMM + h * DD;
    const __nv_bfloat16* loB = g_Klo + ((size_t)b * TT) * DMM + h * DD;
    uint32_t dbase = sb + OFF_K + buf * 36864;
#pragma unroll
    for (int i = 0; i < 4; i++) {
        int q = tid + 256 * i;
        int row = q >> 3, c = q & 7;
        size_t src = (size_t)(j * 128 + row) * DMM + c * 8;
        uint32_t d = dbase + row * KSTRIDE_B + c * 16;
        cpa16(d, hiB + src);
        cpa16(d + 18432, loB + src);
    }
}

__device__ __forceinline__ void compute_tile(const char* smemc, int qs, int kb,
                                             int wm, int wn, int g, int t4,
                                             float* Za, float* Sa, float* Zb, float* Sb) {
    float acc[2][8][4];
#pragma unroll
    for (int mi = 0; mi < 2; mi++)
#pragma unroll
        for (int ni = 0; ni < 8; ni++)
#pragma unroll
            for (int r = 0; r < 4; r++) acc[mi][ni][r] = 0.f;

    const int m0 = qs * 128 + wm * 32;
    const int n0 = wn * 64;
    const char* qhi = smemc + OFF_QHI;
    const char* qlo = smemc + OFF_QLO;
    const char* khi = smemc + OFF_K + kb * 36864;
    const char* klo = khi + 18432;

#pragma unroll
    for (int k0 = 0; k0 < 64; k0 += 16) {
        const int cA = (k0 + 2 * t4) * 2;
        const int cB = cA + 16;
        uint32_t aH[2][4], aL[2][4];
#pragma unroll
        for (int mi = 0; mi < 2; mi++) {
            int rA = (m0 + mi * 16 + g) * KSTRIDE_B;
            int rB = rA + 8 * KSTRIDE_B;
            aH[mi][0] = *(const uint32_t*)(qhi + rA + cA);
            aH[mi][1] = *(const uint32_t*)(qhi + rB + cA);
            aH[mi][2] = *(const uint32_t*)(qhi + rA + cB);
            aH[mi][3] = *(const uint32_t*)(qhi + rB + cB);
            aL[mi][0] = *(const uint32_t*)(qlo + rA + cA);
            aL[mi][1] = *(const uint32_t*)(qlo + rB + cA);
            aL[mi][2] = *(const uint32_t*)(qlo + rA + cB);
            aL[mi][3] = *(const uint32_t*)(qlo + rB + cB);
        }
#pragma unroll
        for (int ni = 0; ni < 8; ni++) {
            int nr = (n0 + ni * 8 + g) * KSTRIDE_B;
            uint32_t bh0 = *(const uint32_t*)(khi + nr + cA);
            uint32_t bh1 = *(const uint32_t*)(khi + nr + cB);
            uint32_t bl0 = *(const uint32_t*)(klo + nr + cA);
            uint32_t bl1 = *(const uint32_t*)(klo + nr + cB);
            mma16816(acc[0][ni], aH[0], bh0, bh1);
            mma16816(acc[1][ni], aH[1], bh0, bh1);
            mma16816(acc[0][ni], aH[0], bl0, bl1);
            mma16816(acc[1][ni], aH[1], bl0, bl1);
            mma16816(acc[0][ni], aL[0], bh0, bh1);
            mma16816(acc[1][ni], aL[1], bh0, bh1);
        }
    }

#pragma unroll
    for (int mi = 0; mi < 2; mi++) {
        float za = 0.f, sa = 0.f, zb = 0.f, sb = 0.f;
#pragma unroll
        for (int ni = 0; ni < 8; ni++) {
            const float* c = acc[mi][ni];
            float y0 = c[0] * C_SCALE; float e0 = ex2f(y0);
            float y1 = c[1] * C_SCALE; float e1 = ex2f(y1);
            float y2 = c[2] * C_SCALE; float e2 = ex2f(y2);
            float y3 = c[3] * C_SCALE; float e3 = ex2f(y3);
            za += e0 + e1; sa = fmaf(y0, e0, sa); sa = fmaf(y1, e1, sa);
            zb += e2 + e3; sb = fmaf(y2, e2, sb); sb = fmaf(y3, e3, sb);
        }
        Za[mi] += za; Sa[mi] += sa; Zb[mi] += zb; Sb[mi] += sb;
    }
}

__global__ void __launch_bounds__(256) kl_mma_kernel() {
    extern __shared__ char dsm[];
    char* smemc = dsm;
    uint32_t sb = smem_u32(dsm);

    int tid = threadIdx.x;
    int wid = tid >> 5, lane = tid & 31;
    int wm = wid & 3, wn = wid >> 2;
    int g = lane >> 2, t4 = lane & 3;
    int qp = blockIdx.x;
    int bh = blockIdx.y;
    int b = bh >> 3, h = bh & 7;
    int q0 = qp * 256;

    {
        const __nv_bfloat16* hiB = g_Qhi + ((size_t)b * TT + q0) * DMM + h * DD;
        const __nv_bfloat16* loB = g_Qlo + ((size_t)b * TT + q0) * DMM + h * DD;
#pragma unroll
        for (int i = 0; i < 8; i++) {
            int q = tid + 256 * i;
            int row = q >> 3, c = q & 7;
            size_t src = (size_t)row * DMM + c * 8;
            uint32_t d = sb + row * KSTRIDE_B + c * 16;
            cpa16(d + OFF_QHI, hiB + src);
            cpa16(d + OFF_QLO, loB + src);
        }
        load_ktile(sb, tid, b, h, 0, 0);
        CP_COMMIT();
    }

    float ZA[2][2] = {}, SA[2][2] = {}, ZB[2][2] = {}, SB[2][2] = {};

    for (int j = 0; j < 16; j++) {
        if (j < 15) { load_ktile(sb, tid, b, h, j + 1, (j + 1) & 1); CP_COMMIT(); }
        if (j < 15) { CP_WAIT1(); } else { CP_WAIT0(); }
        __syncthreads();
        int kb = j & 1;
        compute_tile(smemc, 0, kb, wm, wn, g, t4, ZA[0], SA[0], ZB[0], SB[0]);
        compute_tile(smemc, 1, kb, wm, wn, g, t4, ZA[1], SA[1], ZB[1], SB[1]);
        __syncthreads();
    }

    float* redZ = (float*)smemc;
    float* redS = (float*)smemc + 512;
#pragma unroll
    for (int qs = 0; qs < 2; qs++)
#pragma unroll
        for (int mi = 0; mi < 2; mi++) {
            ZA[qs][mi] += __shfl_xor_sync(0xffffffffu, ZA[qs][mi], 1);
            ZA[qs][mi] += __shfl_xor_sync(0xffffffffu, ZA[qs][mi], 2);
            SA[qs][mi] += __shfl_xor_sync(0xffffffffu, SA[qs][mi], 1);
            SA[qs][mi] += __shfl_xor_sync(0xffffffffu, SA[qs][mi], 2);
            ZB[qs][mi] += __shfl_xor_sync(0xffffffffu, ZB[qs][mi], 1);
            ZB[qs][mi] += __shfl_xor_sync(0xffffffffu, ZB[qs][mi], 2);
            SB[qs][mi] += __shfl_xor_sync(0xffffffffu, SB[qs][mi], 1);
            SB[qs][mi] += __shfl_xor_sync(0xffffffffu, SB[qs][mi], 2);
        }
    __syncthreads();
    if (t4 == 0) {
#pragma unroll
        for (int qs = 0; qs < 2; qs++)
#pragma unroll
            for (int mi = 0; mi < 2; mi++) {
                int rowA = qs * 128 + wm * 32 + mi * 16 + g;
                redZ[rowA * 2 + wn] = ZA[qs][mi];
                redS[rowA * 2 + wn] = SA[qs][mi];
                int rowB = rowA + 8;
                redZ[rowB * 2 + wn] = ZB[qs][mi];
                redS[rowB * 2 + wn] = SB[qs][mi];
            }
    }
    __syncthreads();
    {
        float Z = redZ[2 * tid] + redZ[2 * tid + 1];
        float S = redS[2 * tid] + redS[2 * tid + 1];
        g_KL[(size_t)bh * TT + q0 + tid] = 0.6931471805599453f * (S / Z - __log2f(Z));
        g_Zall[(size_t)bh * TT + q0 + tid] = Z;
    }
}

// ---------------- K4a: reduced attention (warp topk, float4 w@V) -------------
__device__ __forceinline__ bool kl_better(float a, int ia, float b, int ib) {
    return (a > b) || (a == b && ia < ib);
}

// merge two sorted-desc top-3 lists (mine + other) into mine
__device__ __forceinline__ void merge3(float* v, int* ix, const float* bv, const int* bix) {
    float a[6]; int ai[6];
#pragma unroll
    for (int j = 0; j < 3; j++) { a[j] = v[j]; ai[j] = ix[j]; a[3 + j] = bv[j]; ai[3 + j] = bix[j]; }
#pragma unroll
    for (int r = 0; r < 3; r++) {
        int best = r;
#pragma unroll
        for (int j = r + 1; j < 6; j++)
            if (kl_better(a[j], ai[j], a[best], ai[best])) best = j;
        float tv = a[r]; a[r] = a[best]; a[best] = tv;
        int ti = ai[r]; ai[r] = ai[best]; ai[best] = ti;
        v[r] = a[r]; ix[r] = ai[r];
    }
}

__global__ void __launch_bounds__(512) reduced_part_kernel(const float* __restrict__ value) {
    __shared__ __align__(16) float sc[UU][KCHLEN];     // normalized weights
    __shared__ __align__(16) float part[4][UU * DMM];  // per-group partials (24KB)
    __shared__ float wv[16][3];
    __shared__ int   wix[16][3];
    __shared__ float qs[UU][DD];
    __shared__ int   sel[UU];
    __shared__ float invZ[UU];
    int bh = blockIdx.x, kc = blockIdx.y;
    int b = bh >> 3, h = bh & 7;
    int tid = threadIdx.x;
    int wid = tid >> 5, lane = tid & 31;
    const float* kl = g_KL + (size_t)bh * TT;

    // --- phase 1: top-3 via warp shuffles ---
    {
        float v[3] = {-1e30f, -1e30f, -1e30f};
        int ix[3] = {0x7FFFFFFF, 0x7FFFFFFF, 0x7FFFFFFF};
#pragma unroll
        for (int i = 0; i < 4; i++) {
            int t = wid * 128 + i * 32 + lane;
            float val = kl[t];
            if (kl_better(val, t, v[0], ix[0])) {
                v[2] = v[1]; ix[2] = ix[1]; v[1] = v[0]; ix[1] = ix[0]; v[0] = val; ix[0] = t;
            } else if (kl_better(val, t, v[1], ix[1])) {
                v[2] = v[1]; ix[2] = ix[1]; v[1] = val; ix[1] = t;
            } else if (kl_better(val, t, v[2], ix[2])) {
                v[2] = val; ix[2] = t;
            }
        }
#pragma unroll
        for (int off = 16; off >= 1; off >>= 1) {
            float bv[3]; int bix[3];
#pragma unroll
            for (int j = 0; j < 3; j++) {
                bv[j]  = __shfl_xor_sync(0xffffffffu, v[j], off);
                bix[j] = __shfl_xor_sync(0xffffffffu, ix[j], off);
            }
            merge3(v, ix, bv, bix);
        }
        if (lane == 0) {
#pragma unroll
            for (int j = 0; j < 3; j++) { wv[wid][j] = v[j]; wix[wid][j] = ix[j]; }
        }
    }
    __syncthreads();
    if (wid == 0) {
        float v[3]; int ix[3];
        if (lane < 16) {
#pragma unroll
            for (int j = 0; j < 3; j++) { v[j] = wv[lane][j]; ix[j] = wix[lane][j]; }
        } else {
#pragma unroll
            for (int j = 0; j < 3; j++) { v[j] = -1e30f; ix[j] = 0x7FFFFFFF; }
        }
#pragma unroll
        for (int off = 8; off >= 1; off >>= 1) {
            float bv[3]; int bix[3];
#pragma unroll
            for (int j = 0; j < 3; j++) {
                bv[j]  = __shfl_xor_sync(0xffffffffu, v[j], off);
                bix[j] = __shfl_xor_sync(0xffffffffu, ix[j], off);
            }
            merge3(v, ix, bv, bix);
        }
        if (lane == 0) {
#pragma unroll
            for (int j = 0; j < 3; j++) {
                sel[j] = ix[j];
                invZ[j] = 1.0f / g_Zall[(size_t)bh * TT + ix[j]];
                if (kc == 0) g_topk[bh * UU + j] = ix[j];
            }
        }
    }
    __syncthreads();

    // --- phase 2: q rows for the 3 selected queries ---
    if (tid < UU * DD) {
        int u = tid / DD, d = tid % DD;
        qs[u][d] = g_Q[((size_t)b * TT + sel[u]) * DMM + h * DD + d];
    }
    __syncthreads();

    // --- phase 3: normalized weights for this block's 256-k chunk ---
    if (tid < KCHLEN) {
        int k = kc * KCHLEN + tid;
        const float* kr = &g_Kp[((size_t)b * TT + k) * DMM + h * DD];
        float d0 = 0.f, d1 = 0.f, d2 = 0.f;
#pragma unroll
        for (int d = 0; d < DD; d += 4) {
            float4 kv = *(const float4*)&kr[d];
            d0 += qs[0][d] * kv.x + qs[0][d + 1] * kv.y + qs[0][d + 2] * kv.z + qs[0][d + 3] * kv.w;
            d1 += qs[1][d] * kv.x + qs[1][d + 1] * kv.y + qs[1][d + 2] * kv.z + qs[1][d + 3] * kv.w;
            d2 += qs[2][d] * kv.x + qs[2][d + 1] * kv.y + qs[2][d + 2] * kv.z + qs[2][d + 3] * kv.w;
        }
        float s0 = fminf(fmaxf(d0 * 0.125f, -10000.f), 10000.f);
        float s1 = fminf(fmaxf(d1 * 0.125f, -10000.f), 10000.f);
        float s2 = fminf(fmaxf(d2 * 0.125f, -10000.f), 10000.f);
        sc[0][tid] = ex2f(s0 * LOG2E) * invZ[0];
        sc[1][tid] = ex2f(s1 * LOG2E) * invZ[1];
        sc[2][tid] = ex2f(s2 * LOG2E) * invZ[2];
    }
    __syncthreads();

    // --- phase 4: w@V, 4-way k-split x float4 columns ---
    {
        int gq = tid >> 7;         // k-quarter 0..3
        int c4 = tid & 127;        // float4 column group
        const float4* V4 = (const float4*)(value + (size_t)b * TT * DMM);
        int kbase = gq * 64;
        size_t vrow = (size_t)(kc * KCHLEN + kbase) * (DMM / 4) + c4;
        float4 a0 = {0, 0, 0, 0}, a1 = {0, 0, 0, 0}, a2 = {0, 0, 0, 0};
#pragma unroll 4
        for (int kk = 0; kk < 64; kk += 4) {
            float4 w0 = *(const float4*)&sc[0][kbase + kk];
            float4 w1 = *(const float4*)&sc[1][kbase + kk];
            float4 w2 = *(const float4*)&sc[2][kbase + kk];
            float4 va = V4[vrow];
            float4 vb = V4[vrow + 128];
            float4 vc = V4[vrow + 256];
            float4 vd = V4[vrow + 384];
            vrow += 512;
            a0.x = fmaf(w0.x, va.x, a0.x); a0.y = fmaf(w0.x, va.y, a0.y);
            a0.z = fmaf(w0.x, va.z, a0.z); a0.w = fmaf(w0.x, va.w, a0.w);
            a1.x = fmaf(w1.x, va.x, a1.x); a1.y = fmaf(w1.x, va.y, a1.y);
            a1.z = fmaf(w1.x, va.z, a1.z); a1.w = fmaf(w1.x, va.w, a1.w);
            a2.x = fmaf(w2.x, va.x, a2.x); a2.y = fmaf(w2.x, va.y, a2.y);
            a2.z = fmaf(w2.x, va.z, a2.z); a2.w = fmaf(w2.x, va.w, a2.w);
            a0.x = fmaf(w0.y, vb.x, a0.x); a0.y = fmaf(w0.y, vb.y, a0.y);
            a0.z = fmaf(w0.y, vb.z, a0.z); a0.w = fmaf(w0.y, vb.w, a0.w);
            a1.x = fmaf(w1.y, vb.x, a1.x); a1.y = fmaf(w1.y, vb.y, a1.y);
            a1.z = fmaf(w1.y, vb.z, a1.z); a1.w = fmaf(w1.y, vb.w, a1.w);
            a2.x = fmaf(w2.y, vb.x, a2.x); a2.y = fmaf(w2.y, vb.y, a2.y);
            a2.z = fmaf(w2.y, vb.z, a2.z); a2.w = fmaf(w2.y, vb.w, a2.w);
            a0.x = fmaf(w0.z, vc.x, a0.x); a0.y = fmaf(w0.z, vc.y, a0.y);
            a0.z = fmaf(w0.z, vc.z, a0.z); a0.w = fmaf(w0.z, vc.w, a0.w);
            a1.x = fmaf(w1.z, vc.x, a1.x); a1.y = fmaf(w1.z, vc.y, a1.y);
            a1.z = fmaf(w1.z, vc.z, a1.z); a1.w = fmaf(w1.z, vc.w, a1.w);
            a2.x = fmaf(w2.z, vc.x, a2.x); a2.y = fmaf(w2.z, vc.y, a2.y);
            a2.z = fmaf(w2.z, vc.z, a2.z); a2.w = fmaf(w2.z, vc.w, a2.w);
            a0.x = fmaf(w0.w, vd.x, a0.x); a0.y = fmaf(w0.w, vd.y, a0.y);
            a0.z = fmaf(w0.w, vd.z, a0.z); a0.w = fmaf(w0.w, vd.w, a0.w);
            a1.x = fmaf(w1.w, vd.x, a1.x); a1.y = fmaf(w1.w, vd.y, a1.y);
            a1.z = fmaf(w1.w, vd.z, a1.z); a1.w = fmaf(w1.w, vd.w, a1.w);
            a2.x = fmaf(w2.w, vd.x, a2.x); a2.y = fmaf(w2.w, vd.y, a2.y);
            a2.z = fmaf(w2.w, vd.z, a2.z); a2.w = fmaf(w2.w, vd.w, a2.w);
        }
        *(float4*)&part[gq][0 * DMM + c4 * 4] = a0;
        *(float4*)&part[gq][1 * DMM + c4 * 4] = a1;
        *(float4*)&part[gq][2 * DMM + c4 * 4] = a2;
    }
    __syncthreads();

    // --- combine 4 groups, write partial ---
    size_t pb = ((size_t)(bh * KCH + kc) * UU) * DMM + tid;
#pragma unroll
    for (int u = 0; u < UU; u++) {
        float s = part[0][u * DMM + tid] + part[1][u * DMM + tid]
                + part[2][u * DMM + tid] + part[3][u * DMM + tid];
        g_Tpart[pb + (size_t)u * DMM] = s;
    }
}

// ---------------- K4b: combine partials, project through Wv ------------------
__global__ void __launch_bounds__(512) reduced_combine_kernel(const float* __restrict__ Wv,
                                                              const float* __restrict__ bvv) {
    __shared__ float tsh[UU][DMM];
    int bh = blockIdx.x;
    int h = bh & 7;
    int tid = threadIdx.x;

    for (int idx = tid; idx < UU * DMM; idx += 512) {
        int u = idx / DMM, dm = idx % DMM;
        float s = 0.f;
        size_t base = (size_t)bh * KCH * UU * DMM + (size_t)u * DMM + dm;
#pragma unroll
        for (int c = 0; c < KCH; c++) s += g_Tpart[base + (size_t)c * UU * DMM];
        tsh[u][dm] = s;
    }
    __syncthreads();

    if (tid < UU * DD) {
        int u = tid / DD, d = tid % DD;
        const float* wr = &Wv[(size_t)(h * DD + d) * DMM];
        float o = bvv[h * DD + d];
#pragma unroll 8
        for (int j = 0; j < DMM; j++) o = fmaf(tsh[u][j], wr[j], o);
        g_outred[(bh * UU + u) * DD + d] = o;
    }
}

// ---------------- K5a: fill output with bo (float4) --------------------------
__global__ void fill_kernel(float4* __restrict__ y4, const float4* __restrict__ bo4) {
    int i = blockIdx.x * 512 + threadIdx.x;
    y4[i] = bo4[i & 127];
}

// ---------------- K5b: scatter-project selected rows through Wo --------------
__global__ void scatter_kernel(const float* __restrict__ Wo,
                               const float* __restrict__ bo,
                               float* __restrict__ y) {
    int b = blockIdx.x / (HH * UU);
    int e = blockIdx.x % (HH * UU);
    int h = e / UU, u = e % UU;
    int te = g_topk[(b * HH + h) * UU + u];
    int j = threadIdx.x;                     // 512 threads
    float acc = bo[j];
    for (int e2 = 0; e2 < HH * UU; e2++) {
        int h2 = e2 / UU, u2 = e2 % UU;
        if (g_topk[(b * HH + h2) * UU + u2] == te) {
            const float* orv = &g_outred[((b * HH + h2) * UU + u2) * DD];
            const float* wr  = &Wo[(size_t)j * DMM + h2 * DD];
#pragma unroll
            for (int d = 0; d < DD; d += 4) {
                float4 w4 = *(const float4*)&wr[d];
                acc += orv[d] * w4.x + orv[d + 1] * w4.y + orv[d + 2] * w4.z + orv[d + 3] * w4.w;
            }
        }
    }
    y[((size_t)b * TT + te) * DMM + j] = acc;
}

// ---------------- launcher ---------------------------------------------------
extern "C" void kernel_launch(void* const* d_in, const int* in_sizes, int n_in,
                              void* d_out, int out_size) {
    const float* query = (const float*)d_in[0];
    const float* key   = (const float*)d_in[1];
    const float* value = (const float*)d_in[2];
    const float* Wq    = (const float*)d_in[3];
    const float* bq    = (const float*)d_in[4];
    const float* Wk    = (const float*)d_in[5];
    const float* bk    = (const float*)d_in[6];
    const float* Wv    = (const float*)d_in[7];
    const float* bv    = (const float*)d_in[8];
    const float* Wo    = (const float*)d_in[9];
    const float* bo    = (const float*)d_in[10];
    float* y = (float*)d_out;

    cudaFuncSetAttribute(kl_mma_kernel, cudaFuncAttributeMaxDynamicSharedMemorySize, KL_SMEM);
    cudaFuncSetAttribute(proj_mma_kernel, cudaFuncAttributeMaxDynamicSharedMemorySize, PJ_SMEM);

    const int nconv = (2 * (XSZ / 4) + 2 * (WSZ / 4) + 255) / 256;
    convert_kernel<<<nconv, 256>>>((const float4*)query, (const float4*)key,
                                   (const float4*)Wq, (const float4*)Wk);

    dim3 pg(BB * TT / 128, DMM / 64, 2);
    proj_mma_kernel<<<pg, 256, PJ_SMEM>>>(bq, bk);

    dim3 kg(8, BB * HH);                       // 128 blocks, one wave
    kl_mma_kernel<<<kg, 256, KL_SMEM>>>();

    dim3 rg(BB * HH, KCH);                     // 128 blocks
    reduced_part_kernel<<<rg, 512>>>(value);
    reduced_combine_kernel<<<BB * HH, 512>>>(Wv, bv);

    fill_kernel<<<(BB * TT * DMM) / 4 / 512, 512>>>((float4*)y, (const float4*)bo);
    scatter_kernel<<<BB * HH * UU, 512>>>(Wo, bo, y);
}